// round 8
// baseline (speedup 1.0000x reference)
#include <cuda_runtime.h>
#include <cuda_fp16.h>
#include <math.h>
#include <cstdint>

#define NN   8192
#define DIN  256
#define DOUT 128

// ---------------- scratch ----------------
__device__ float g_h[NN * DOUT];                 // 4 MB fp32 h
__device__ float g_a1[NN], g_a2[NN];
__device__ float g_e1p[NN], g_e1n[NN];           // exp(a1), exp(0.01*a1)
__device__ float g_e2p[NN], g_e2n[NN];           // exp(a2), exp(0.01*a2)
__device__ unsigned short g_hTf[DOUT * NN];      // fp16 hT [d][j]

// ---------------- helpers ----------------
__device__ __forceinline__ uint32_t smem_u32(const void* p) {
    uint32_t a;
    asm("{ .reg .u64 t; cvta.to.shared.u64 t, %1; cvt.u32.u64 %0, t; }" : "=r"(a) : "l"(p));
    return a;
}
#define LDSM4(r0, r1, r2, r3, addr)                                            \
    asm volatile("ldmatrix.sync.aligned.m8n8.x4.shared.b16 {%0,%1,%2,%3}, [%4];" \
        : "=r"(r0), "=r"(r1), "=r"(r2), "=r"(r3) : "r"(addr))
#define MMA_F16(c, a, b0, b1)                                                  \
    asm volatile("mma.sync.aligned.m16n8k16.row.col.f32.f16.f16.f32 "          \
        "{%0,%1,%2,%3},{%4,%5,%6,%7},{%8,%9},{%0,%1,%2,%3};"                   \
        : "+f"((c)[0]), "+f"((c)[1]), "+f"((c)[2]), "+f"((c)[3])               \
        : "r"((a)[0]), "r"((a)[1]), "r"((a)[2]), "r"((a)[3]), "r"(b0), "r"(b1))
#define CP16(dst, src)                                                         \
    asm volatile("cp.async.ca.shared.global [%0], [%1], 16;"                   \
        :: "r"(dst), "l"(src) : "memory")
#define CP_COMMIT() asm volatile("cp.async.commit_group;" ::: "memory")
#define CP_WAIT0()  asm volatile("cp.async.wait_group 0;" ::: "memory")
#define BAR_SYNC(id)   asm volatile("bar.sync %0, 512;"   :: "r"(id) : "memory")
#define BAR_ARRIVE(id) asm volatile("bar.arrive %0, 512;" :: "r"(id) : "memory")

// ============================================================
// Kernel 1: h = feat @ W^T + b
// ============================================================
__global__ __launch_bounds__(256) void gemm_h_kernel(
    const float* __restrict__ feat, const float* __restrict__ W, const float* __restrict__ bias)
{
    __shared__ float fs[64][32];
    __shared__ float ws[32][132];
    const int t = threadIdx.x;
    const int i0 = blockIdx.x * 64;
    const int ty = t >> 4, tx = t & 15;
    float acc[4][8];
#pragma unroll
    for (int r = 0; r < 4; r++)
#pragma unroll
        for (int c = 0; c < 8; c++) acc[r][c] = 0.f;

    for (int k0 = 0; k0 < DIN; k0 += 32) {
#pragma unroll
        for (int v = 0; v < 2; v++) {
            int f = v * 256 + t, row = f >> 3, off = (f & 7) * 4;
            *(float4*)&fs[row][off] = *(const float4*)&feat[(size_t)(i0 + row) * DIN + k0 + off];
        }
        {
            int c = t >> 1, half = (t & 1) * 16;
#pragma unroll
            for (int q = 0; q < 4; q++) {
                float4 wv = *(const float4*)&W[(size_t)c * DIN + k0 + half + q * 4];
                ws[half + q * 4 + 0][c] = wv.x; ws[half + q * 4 + 1][c] = wv.y;
                ws[half + q * 4 + 2][c] = wv.z; ws[half + q * 4 + 3][c] = wv.w;
            }
        }
        __syncthreads();
#pragma unroll
        for (int kk = 0; kk < 32; kk++) {
            float a[4];
#pragma unroll
            for (int r = 0; r < 4; r++) a[r] = fs[ty * 4 + r][kk];
            float4 b0 = *(const float4*)&ws[kk][tx * 8];
            float4 b1 = *(const float4*)&ws[kk][tx * 8 + 4];
            float bb[8] = {b0.x, b0.y, b0.z, b0.w, b1.x, b1.y, b1.z, b1.w};
#pragma unroll
            for (int r = 0; r < 4; r++)
#pragma unroll
                for (int c = 0; c < 8; c++) acc[r][c] += a[r] * bb[c];
        }
        __syncthreads();
    }
#pragma unroll
    for (int r = 0; r < 4; r++) {
        int gi = i0 + ty * 4 + r;
#pragma unroll
        for (int c = 0; c < 8; c++)
            g_h[(size_t)gi * DOUT + tx * 8 + c] = acc[r][c] + bias[tx * 8 + c];
    }
}

// ============================================================
// Kernel 2: a1,a2 + factorized exp tables
// ============================================================
__global__ __launch_bounds__(256) void prep_kernel(
    const float* __restrict__ w1, const float* __restrict__ b1,
    const float* __restrict__ w2, const float* __restrict__ b2)
{
    const int warp = threadIdx.x >> 5, lane = threadIdx.x & 31;
    const int i = blockIdx.x * 8 + warp;
    float s1 = 0.f, s2 = 0.f;
#pragma unroll
    for (int d = lane; d < DOUT; d += 32) {
        float hv = g_h[(size_t)i * DOUT + d];
        s1 += hv * w1[d]; s2 += hv * w2[d];
    }
#pragma unroll
    for (int o = 16; o > 0; o >>= 1) {
        s1 += __shfl_xor_sync(0xffffffffu, s1, o);
        s2 += __shfl_xor_sync(0xffffffffu, s2, o);
    }
    if (lane == 0) {
        float a1 = s1 + b1[0], a2 = s2 + b2[0];
        g_a1[i] = a1; g_a2[i] = a2;
        g_e1p[i] = expf(a1); g_e1n[i] = expf(0.01f * a1);
        g_e2p[i] = expf(a2); g_e2n[i] = expf(0.01f * a2);
    }
}

// ============================================================
// Kernel 3: transpose h -> fp16 hT [d][j]
// ============================================================
__global__ __launch_bounds__(256) void convert_hT_kernel()
{
    __shared__ float s[32][33];
    const int i0 = blockIdx.x * 32, d0 = blockIdx.y * 32;
    const int lx = threadIdx.x & 31, ly = threadIdx.x >> 5;
#pragma unroll
    for (int q = 0; q < 4; q++) {
        int il = ly + q * 8;
        s[il][lx] = g_h[(size_t)(i0 + il) * DOUT + d0 + lx];
    }
    __syncthreads();
#pragma unroll
    for (int q = 0; q < 4; q++) {
        int dl = ly + q * 8;
        __half hv = __float2half_rn(s[lx][dl]);
        g_hTf[(size_t)(d0 + dl) * NN + i0 + lx] = *reinterpret_cast<unsigned short*>(&hv);
    }
}

// ============================================================
// Kernel 4: warp-specialized fused attention.
// 128 blocks x 512 threads; CTA M=64 x N=128, KT=128, 64 tiles.
// Warps 0-7: consumers (pure ldmatrix+mma, all 8 ksteps, warp m32n32).
// Warps 8-15: producers (adj LDG + weight-gen + STS A + cp.async B).
// 3-stage ring, 48KB/stage; named barriers full[s]=1+s, empty[s]=4+s.
// ============================================================
#define KT      128
#define ITERS   (NN / KT)
#define NSTAGE  3
#define A_T     0
#define B_T     16384
#define STAGE_B 49152
#define ATTN_SMEM (NSTAGE * STAGE_B)

__global__ __launch_bounds__(512) void attn_mma_kernel(
    const int* __restrict__ adj, float* __restrict__ out)
{
    extern __shared__ char smem[];
    __shared__ float den_s[64];
    const uint32_t sb = smem_u32(smem);
    const int t = threadIdx.x, lane = t & 31, wid = t >> 5;
    const int i0 = blockIdx.x * 64;

    if (wid >= 8) {
        // ================= PRODUCER =================
        const int t2 = t - 256;
        const int jq = t2 & 31, rw = t2 >> 5;          // lane = jq
        float a1r[8], e1pv[8], e1nv[8], den[8];
        const int* adjp[8];
        uint32_t aSts[8];
#pragma unroll
        for (int u = 0; u < 8; u++) {
            int row = rw + 8 * u;
            int gi = i0 + row;
            a1r[u] = g_a1[gi]; e1pv[u] = g_e1p[gi]; e1nv[u] = g_e1n[gi];
            den[u] = 0.f;
            adjp[u] = adj + (size_t)gi * NN + jq * 4;
            aSts[u] = row * 256 + ((jq * 8) ^ ((row & 7) << 4));
        }
        // B cp.async mapping: row bn (=d), half bh (128B each)
        const int bn = t2 >> 1, bh = t2 & 1;
        const unsigned short* srcB = g_hTf + (size_t)bn * NN + bh * 64;
        uint32_t bOff[8];
#pragma unroll
        for (int q = 0; q < 8; q++)
            bOff[q] = bn * 256 + (((uint32_t)(bh * 128 + q * 16)) ^ ((bn & 7) << 4));

        int4 adjR[8]; float4 a2R, epR, enR;
        auto prefetch = [&](int J0) {
#pragma unroll
            for (int u = 0; u < 8; u++) adjR[u] = *(const int4*)(adjp[u] + J0);
            a2R = *(const float4*)&g_a2[J0 + jq * 4];
            epR = *(const float4*)&g_e2p[J0 + jq * 4];
            enR = *(const float4*)&g_e2n[J0 + jq * 4];
        };
        prefetch(0);

        for (int k = 0; k < ITERS; k++) {
            const int s = k % NSTAGE;
            const uint32_t stb = (uint32_t)s * STAGE_B;
            if (k >= NSTAGE) BAR_SYNC(4 + s);          // wait stage empty
            // B: cp.async (1 KB per thread per tile covered by group)
            {
                const unsigned short* sB = srcB + k * KT;
#pragma unroll
                for (int q = 0; q < 8; q++)
                    CP16(sb + stb + B_T + bOff[q], (const void*)(sB + q * 8));
                CP_COMMIT();
            }
            // weights for tile k -> STS A
            {
                float a2a[4] = {a2R.x, a2R.y, a2R.z, a2R.w};
                float epa[4] = {epR.x, epR.y, epR.z, epR.w};
                float ena[4] = {enR.x, enR.y, enR.z, enR.w};
#pragma unroll
                for (int u = 0; u < 8; u++) {
                    int avi[4] = {adjR[u].x, adjR[u].y, adjR[u].z, adjR[u].w};
                    float w[4];
#pragma unroll
                    for (int q = 0; q < 4; q++) {
                        float ta = a1r[u] + a2a[q];
                        float e1 = (ta >= 0.f) ? e1pv[u] : e1nv[u];
                        float e2 = (ta >= 0.f) ? epa[q] : ena[q];
                        float wq = e1 * e2;
                        wq = avi[q] ? wq : 0.f;
                        den[u] += wq;
                        w[q] = wq;
                    }
                    __half2 p0 = __floats2half2_rn(w[0], w[1]);
                    __half2 p1 = __floats2half2_rn(w[2], w[3]);
                    *(uint2*)(smem + stb + A_T + aSts[u]) =
                        make_uint2(*reinterpret_cast<uint32_t*>(&p0),
                                   *reinterpret_cast<uint32_t*>(&p1));
                }
            }
            if (k + 1 < ITERS) prefetch((k + 1) * KT); // overlap LDG with wait
            CP_WAIT0();                                // B(k) landed
            BAR_ARRIVE(1 + s);                         // stage full
        }
        // denominator: reduce over lanes (lane = jq)
#pragma unroll
        for (int o = 16; o > 0; o >>= 1)
#pragma unroll
            for (int u = 0; u < 8; u++) den[u] += __shfl_xor_sync(0xffffffffu, den[u], o);
        if (lane == 0)
#pragma unroll
            for (int u = 0; u < 8; u++) den_s[rw + 8 * u] = den[u];
        __syncthreads();   // publish den_s; consumers waiting here
    } else {
        // ================= CONSUMER =================
        const int wm = wid >> 2, wn = wid & 3;
        uint32_t aRowOff[2], bRowOff[2];
#pragma unroll
        for (int m = 0; m < 2; m++)
            aRowOff[m] = (uint32_t)(wm * 32 + m * 16 + (lane & 15)) * 256;
#pragma unroll
        for (int p = 0; p < 2; p++)
            bRowOff[p] = (uint32_t)(wn * 32 + p * 16 + (lane & 7) + ((lane >> 4) << 3)) * 256;
        const uint32_t mXor = (lane & 7) << 4;
        const uint32_t aCol = (lane >> 4) << 4;
        const uint32_t bCol = (lane & 8) << 1;

        float acc[32];
#pragma unroll
        for (int i = 0; i < 32; i++) acc[i] = 0.f;

        for (int k = 0; k < ITERS; k++) {
            const int s = k % NSTAGE;
            const uint32_t ab = sb + (uint32_t)s * STAGE_B;
            BAR_SYNC(1 + s);                           // wait stage full
#pragma unroll
            for (int si = 0; si < 8; si++) {
                const uint32_t cs = si * 32;
                uint32_t aa[2][4], bb[2][4];
                const uint32_t ca = (cs + aCol) ^ mXor;
                const uint32_t cb = (cs + bCol) ^ mXor;
#pragma unroll
                for (int m = 0; m < 2; m++)
                    LDSM4(aa[m][0], aa[m][1], aa[m][2], aa[m][3], ab + A_T + aRowOff[m] + ca);
#pragma unroll
                for (int p = 0; p < 2; p++)
                    LDSM4(bb[p][0], bb[p][1], bb[p][2], bb[p][3], ab + B_T + bRowOff[p] + cb);
#pragma unroll
                for (int m = 0; m < 2; m++)
#pragma unroll
                    for (int nt = 0; nt < 4; nt++) {
                        float* c = &acc[(m * 4 + nt) * 4];
                        uint32_t b0 = bb[nt >> 1][(nt & 1) * 2], b1 = bb[nt >> 1][(nt & 1) * 2 + 1];
                        MMA_F16(c, aa[m], b0, b1);
                    }
            }
            BAR_ARRIVE(4 + s);                         // stage empty
        }
        __syncthreads();   // den_s ready

        // epilogue: divide by denominator, store
#pragma unroll
        for (int m = 0; m < 2; m++) {
            int r0 = wm * 32 + m * 16 + (lane >> 2);
            float inv0 = 1.0f / den_s[r0];
            float inv1 = 1.0f / den_s[r0 + 8];
#pragma unroll
            for (int nt = 0; nt < 4; nt++) {
                float* c = &acc[(m * 4 + nt) * 4];
                int col = wn * 32 + nt * 8 + (lane & 3) * 2;
                *(float2*)&out[(size_t)(i0 + r0) * DOUT + col] =
                    make_float2(c[0] * inv0, c[1] * inv0);
                *(float2*)&out[(size_t)(i0 + r0 + 8) * DOUT + col] =
                    make_float2(c[2] * inv1, c[3] * inv1);
            }
        }
    }
}

// ============================================================
extern "C" void kernel_launch(void* const* d_in, const int* in_sizes, int n_in,
                              void* d_out, int out_size)
{
    const float* feat = (const float*)d_in[0];
    const int*   adj  = (const int*)d_in[1];
    const float* W    = (const float*)d_in[2];
    const float* b    = (const float*)d_in[3];
    const float* w1   = (const float*)d_in[4];
    const float* b1   = (const float*)d_in[5];
    const float* w2   = (const float*)d_in[6];
    const float* b2   = (const float*)d_in[7];
    float* out = (float*)d_out;

    static bool attr_set = false;
    if (!attr_set) {
        cudaFuncSetAttribute(attn_mma_kernel,
                             cudaFuncAttributeMaxDynamicSharedMemorySize, ATTN_SMEM);
        attr_set = true;
    }

    gemm_h_kernel<<<NN / 64, 256>>>(feat, W, b);
    prep_kernel<<<NN / 8, 256>>>(w1, b1, w2, b2);
    convert_hT_kernel<<<dim3(NN / 32, DOUT / 32), 256>>>();
    attn_mma_kernel<<<NN / 64, 512, ATTN_SMEM>>>(adj, out);
}

// round 9
// speedup vs baseline: 1.4108x; 1.4108x over previous
#include <cuda_runtime.h>
#include <cuda_fp16.h>
#include <math.h>
#include <cstdint>

#define NN   8192
#define DIN  256
#define DOUT 128

// ---------------- scratch ----------------
__device__ float g_h[NN * DOUT];                 // 4 MB fp32 h
__device__ float g_a1[NN], g_a2[NN];
__device__ float g_e1p[NN], g_e1n[NN];           // exp(a1), exp(0.01*a1)
__device__ float g_e2p[NN], g_e2n[NN];           // exp(a2), exp(0.01*a2)
__device__ unsigned short g_hTf[DOUT * NN];      // fp16 hT [d][j]

// ---------------- helpers ----------------
__device__ __forceinline__ uint32_t smem_u32(const void* p) {
    uint32_t a;
    asm("{ .reg .u64 t; cvta.to.shared.u64 t, %1; cvt.u32.u64 %0, t; }" : "=r"(a) : "l"(p));
    return a;
}
#define LDSM4(r0, r1, r2, r3, addr)                                            \
    asm volatile("ldmatrix.sync.aligned.m8n8.x4.shared.b16 {%0,%1,%2,%3}, [%4];" \
        : "=r"(r0), "=r"(r1), "=r"(r2), "=r"(r3) : "r"(addr))
#define MMA_F16(c, a, b0, b1)                                                  \
    asm volatile("mma.sync.aligned.m16n8k16.row.col.f32.f16.f16.f32 "          \
        "{%0,%1,%2,%3},{%4,%5,%6,%7},{%8,%9},{%0,%1,%2,%3};"                   \
        : "+f"((c)[0]), "+f"((c)[1]), "+f"((c)[2]), "+f"((c)[3])               \
        : "r"((a)[0]), "r"((a)[1]), "r"((a)[2]), "r"((a)[3]), "r"(b0), "r"(b1))
#define CP16(dst, src)                                                         \
    asm volatile("cp.async.ca.shared.global [%0], [%1], 16;"                   \
        :: "r"(dst), "l"(src) : "memory")
#define CP_COMMIT() asm volatile("cp.async.commit_group;" ::: "memory")
#define CP_WAIT0()  asm volatile("cp.async.wait_group 0;" ::: "memory")
#define BARH(id)    asm volatile("bar.sync %0, 256;" :: "r"(id) : "memory")

// ============================================================
// Kernel 1: h = feat @ W^T + b
// ============================================================
__global__ __launch_bounds__(256) void gemm_h_kernel(
    const float* __restrict__ feat, const float* __restrict__ W, const float* __restrict__ bias)
{
    __shared__ float fs[64][32];
    __shared__ float ws[32][132];
    const int t = threadIdx.x;
    const int i0 = blockIdx.x * 64;
    const int ty = t >> 4, tx = t & 15;
    float acc[4][8];
#pragma unroll
    for (int r = 0; r < 4; r++)
#pragma unroll
        for (int c = 0; c < 8; c++) acc[r][c] = 0.f;

    for (int k0 = 0; k0 < DIN; k0 += 32) {
#pragma unroll
        for (int v = 0; v < 2; v++) {
            int f = v * 256 + t, row = f >> 3, off = (f & 7) * 4;
            *(float4*)&fs[row][off] = *(const float4*)&feat[(size_t)(i0 + row) * DIN + k0 + off];
        }
        {
            int c = t >> 1, half = (t & 1) * 16;
#pragma unroll
            for (int q = 0; q < 4; q++) {
                float4 wv = *(const float4*)&W[(size_t)c * DIN + k0 + half + q * 4];
                ws[half + q * 4 + 0][c] = wv.x; ws[half + q * 4 + 1][c] = wv.y;
                ws[half + q * 4 + 2][c] = wv.z; ws[half + q * 4 + 3][c] = wv.w;
            }
        }
        __syncthreads();
#pragma unroll
        for (int kk = 0; kk < 32; kk++) {
            float a[4];
#pragma unroll
            for (int r = 0; r < 4; r++) a[r] = fs[ty * 4 + r][kk];
            float4 b0 = *(const float4*)&ws[kk][tx * 8];
            float4 b1 = *(const float4*)&ws[kk][tx * 8 + 4];
            float bb[8] = {b0.x, b0.y, b0.z, b0.w, b1.x, b1.y, b1.z, b1.w};
#pragma unroll
            for (int r = 0; r < 4; r++)
#pragma unroll
                for (int c = 0; c < 8; c++) acc[r][c] += a[r] * bb[c];
        }
        __syncthreads();
    }
#pragma unroll
    for (int r = 0; r < 4; r++) {
        int gi = i0 + ty * 4 + r;
#pragma unroll
        for (int c = 0; c < 8; c++)
            g_h[(size_t)gi * DOUT + tx * 8 + c] = acc[r][c] + bias[tx * 8 + c];
    }
}

// ============================================================
// Kernel 2: a1,a2 + factorized exp tables
// ============================================================
__global__ __launch_bounds__(256) void prep_kernel(
    const float* __restrict__ w1, const float* __restrict__ b1,
    const float* __restrict__ w2, const float* __restrict__ b2)
{
    const int warp = threadIdx.x >> 5, lane = threadIdx.x & 31;
    const int i = blockIdx.x * 8 + warp;
    float s1 = 0.f, s2 = 0.f;
#pragma unroll
    for (int d = lane; d < DOUT; d += 32) {
        float hv = g_h[(size_t)i * DOUT + d];
        s1 += hv * w1[d]; s2 += hv * w2[d];
    }
#pragma unroll
    for (int o = 16; o > 0; o >>= 1) {
        s1 += __shfl_xor_sync(0xffffffffu, s1, o);
        s2 += __shfl_xor_sync(0xffffffffu, s2, o);
    }
    if (lane == 0) {
        float a1 = s1 + b1[0], a2 = s2 + b2[0];
        g_a1[i] = a1; g_a2[i] = a2;
        g_e1p[i] = expf(a1); g_e1n[i] = expf(0.01f * a1);
        g_e2p[i] = expf(a2); g_e2n[i] = expf(0.01f * a2);
    }
}

// ============================================================
// Kernel 3: transpose h -> fp16 hT [d][j]
// ============================================================
__global__ __launch_bounds__(256) void convert_hT_kernel()
{
    __shared__ float s[32][33];
    const int i0 = blockIdx.x * 32, d0 = blockIdx.y * 32;
    const int lx = threadIdx.x & 31, ly = threadIdx.x >> 5;
#pragma unroll
    for (int q = 0; q < 4; q++) {
        int il = ly + q * 8;
        s[il][lx] = g_h[(size_t)(i0 + il) * DOUT + d0 + lx];
    }
    __syncthreads();
#pragma unroll
    for (int q = 0; q < 4; q++) {
        int dl = ly + q * 8;
        __half hv = __float2half_rn(s[lx][dl]);
        g_hTf[(size_t)(d0 + dl) * NN + i0 + lx] = *reinterpret_cast<unsigned short*>(&hv);
    }
}

// ============================================================
// Kernel 4: fused attention, two independent 256-thread sub-CTAs.
// 128 blocks x 512 threads; CTA M=64 x N=128.
// Half h (warps 8h..8h+7) handles j in [h*4096, (h+1)*4096), KT=64,
// 64 iters, own double buffer + named barriers (1,2)/(3,4).
// SMEM: half h at h*49152; stage s at s*24576: A 8K | B 16K.
// Partial accumulators + denominators merged at the end.
// ============================================================
#define KT      64
#define HITERS  (4096 / KT)
#define HALF_B  49152
#define STAGE_B 24576
#define A_T     0
#define B_T     8192
#define ATTN_SMEM (2 * HALF_B)

__global__ __launch_bounds__(512) void attn_mma_kernel(
    const int* __restrict__ adj, float* __restrict__ out)
{
    extern __shared__ char smem[];
    __shared__ float den_s2[2][64];
    const uint32_t sb = smem_u32(smem);
    const int t = threadIdx.x, lane = t & 31, wid = t >> 5;
    const int i0 = blockIdx.x * 64;
    const int half = wid >> 3;               // 0 or 1
    const int t2 = t & 255;                  // id within half
    const int jbase = half * 4096;
    const uint32_t hb = (uint32_t)half * HALF_B;
    const int bar0 = 1 + 2 * half, bar1 = 2 + 2 * half;

    // ---- weight-gen mapping: rows rq+16u (u<4), j's jq*4..+3 (within half) ----
    const int jq = t2 & 15, rq = t2 >> 4;
    float a1r[4], e1pv[4], e1nv[4], den[4];
    const int* adjp[4];
    uint32_t aSts[4];
#pragma unroll
    for (int u = 0; u < 4; u++) {
        int row = rq + 16 * u;
        int gi = i0 + row;
        a1r[u] = g_a1[gi]; e1pv[u] = g_e1p[gi]; e1nv[u] = g_e1n[gi];
        den[u] = 0.f;
        adjp[u] = adj + (size_t)gi * NN + jbase + jq * 4;
        aSts[u] = row * 128 + ((jq * 8) ^ ((row & 7) << 4));
    }

    // ---- B cp.async mapping: row bn (=d, 128), half-row bh (64B) ----
    const int bn = t2 >> 1, bh = t2 & 1;
    const unsigned short* srcB = g_hTf + (size_t)bn * NN + jbase + bh * 32;
    uint32_t bOff[4];
#pragma unroll
    for (int q = 0; q < 4; q++)
        bOff[q] = bn * 128 + (((uint32_t)(bh * 64 + q * 16)) ^ ((bn & 7) << 4));

    // ---- mma mapping: 8 warps/half, 2m x 4n, warp m32n32, all 4 ksteps ----
    const int w8 = wid & 7;
    const int wm = w8 >> 2, wn = w8 & 3;
    uint32_t aRowOff[2], bRowOff[2];
#pragma unroll
    for (int m = 0; m < 2; m++)
        aRowOff[m] = (uint32_t)(wm * 32 + m * 16 + (lane & 15)) * 128;
#pragma unroll
    for (int p = 0; p < 2; p++)
        bRowOff[p] = (uint32_t)(wn * 32 + p * 16 + (lane & 7) + ((lane >> 4) << 3)) * 128;
    const uint32_t mXor = (lane & 7) << 4;
    const uint32_t aCol = (lane >> 4) << 4;
    const uint32_t bCol = (lane & 8) << 1;

    float acc[32];
#pragma unroll
    for (int i = 0; i < 32; i++) acc[i] = 0.f;

    // ---- prefetch regs (tile k) ----
    int4 adjR[4]; float4 a2R, epR, enR;
    auto prefetch = [&](int J0) {
#pragma unroll
        for (int u = 0; u < 4; u++) adjR[u] = *(const int4*)(adjp[u] + J0);
        a2R = *(const float4*)&g_a2[jbase + J0 + jq * 4];
        epR = *(const float4*)&g_e2p[jbase + J0 + jq * 4];
        enR = *(const float4*)&g_e2n[jbase + J0 + jq * 4];
    };
    auto cpB = [&](uint32_t stb, int J0) {
#pragma unroll
        for (int q = 0; q < 4; q++)
            CP16(sb + hb + stb + B_T + bOff[q], (const void*)(srcB + J0 + q * 8));
        CP_COMMIT();
    };

    // ---- prologue ----
    cpB(0, 0);
    prefetch(0);

    for (int k = 0; k < HITERS; k++) {
        const uint32_t stb = (k & 1) ? STAGE_B : 0;
        const uint32_t ostb = STAGE_B - stb;

        // ---- compute weights for tile k (regs prefetched >1 MMA-phase ago) ----
        uint2 whi[4];
        {
            float a2a[4] = {a2R.x, a2R.y, a2R.z, a2R.w};
            float epa[4] = {epR.x, epR.y, epR.z, epR.w};
            float ena[4] = {enR.x, enR.y, enR.z, enR.w};
#pragma unroll
            for (int u = 0; u < 4; u++) {
                int avi[4] = {adjR[u].x, adjR[u].y, adjR[u].z, adjR[u].w};
                float w[4];
#pragma unroll
                for (int q = 0; q < 4; q++) {
                    float ta = a1r[u] + a2a[q];
                    float e1 = (ta >= 0.f) ? e1pv[u] : e1nv[u];
                    float e2 = (ta >= 0.f) ? epa[q] : ena[q];
                    float wq = e1 * e2;
                    wq = avi[q] ? wq : 0.f;
                    den[u] += wq;
                    w[q] = wq;
                }
                __half2 p0 = __floats2half2_rn(w[0], w[1]);
                __half2 p1 = __floats2half2_rn(w[2], w[3]);
                whi[u] = make_uint2(*reinterpret_cast<uint32_t*>(&p0),
                                    *reinterpret_cast<uint32_t*>(&p1));
            }
        }

        BARH(bar0);        // stage stb free (readers of iter k-2 done)
#pragma unroll
        for (int u = 0; u < 4; u++)
            *(uint2*)(smem + hb + stb + A_T + aSts[u]) = whi[u];
        CP_WAIT0();        // B(k) landed
        BARH(bar1);        // A+B visible to all half warps

        // issue next tile's loads EARLY so latency hides under MMA + weight-gen
        if (k + 1 < HITERS) { cpB(ostb, (k + 1) * KT); prefetch((k + 1) * KT); }

        // ---- mma: 4 k16 steps ----
        const uint32_t ab = sb + hb + stb;
#pragma unroll
        for (int si = 0; si < 4; si++) {
            const uint32_t cs = si * 32;
            uint32_t aa[2][4], bb[2][4];
            const uint32_t ca = (cs + aCol) ^ mXor;
            const uint32_t cb = (cs + bCol) ^ mXor;
#pragma unroll
            for (int m = 0; m < 2; m++)
                LDSM4(aa[m][0], aa[m][1], aa[m][2], aa[m][3], ab + A_T + aRowOff[m] + ca);
#pragma unroll
            for (int p = 0; p < 2; p++)
                LDSM4(bb[p][0], bb[p][1], bb[p][2], bb[p][3], ab + B_T + bRowOff[p] + cb);
#pragma unroll
            for (int m = 0; m < 2; m++)
#pragma unroll
                for (int nt = 0; nt < 4; nt++) {
                    float* c = &acc[(m * 4 + nt) * 4];
                    uint32_t b0 = bb[nt >> 1][(nt & 1) * 2], b1 = bb[nt >> 1][(nt & 1) * 2 + 1];
                    MMA_F16(c, aa[m], b0, b1);
                }
        }
    }

    // ---- denominator: reduce over jq (lane&15) ----
#pragma unroll
    for (int o = 8; o > 0; o >>= 1)
#pragma unroll
        for (int u = 0; u < 4; u++) den[u] += __shfl_xor_sync(0xffffffffu, den[u], o);
    if ((lane & 15) == 0)
#pragma unroll
        for (int u = 0; u < 4; u++) den_s2[half][rq + 16 * u] = den[u];

    // ---- merge halves ----
    float* out_s = (float*)smem;   // 64 x 130 floats (buffers dead)
    __syncthreads();
    if (half == 1) {
#pragma unroll
        for (int m = 0; m < 2; m++) {
            int r0 = wm * 32 + m * 16 + (lane >> 2);
#pragma unroll
            for (int nt = 0; nt < 4; nt++) {
                float* c = &acc[(m * 4 + nt) * 4];
                int col = wn * 32 + nt * 8 + (lane & 3) * 2;
                *(float2*)&out_s[r0 * 130 + col]       = make_float2(c[0], c[1]);
                *(float2*)&out_s[(r0 + 8) * 130 + col] = make_float2(c[2], c[3]);
            }
        }
    }
    __syncthreads();
    if (half == 0) {
#pragma unroll
        for (int m = 0; m < 2; m++) {
            int r0 = wm * 32 + m * 16 + (lane >> 2);
            float inv0 = 1.0f / (den_s2[0][r0]     + den_s2[1][r0]);
            float inv1 = 1.0f / (den_s2[0][r0 + 8] + den_s2[1][r0 + 8]);
#pragma unroll
            for (int nt = 0; nt < 4; nt++) {
                float* c = &acc[(m * 4 + nt) * 4];
                int col = wn * 32 + nt * 8 + (lane & 3) * 2;
                float2 p0 = *(const float2*)&out_s[r0 * 130 + col];
                float2 p1 = *(const float2*)&out_s[(r0 + 8) * 130 + col];
                *(float2*)&out[(size_t)(i0 + r0) * DOUT + col] =
                    make_float2((c[0] + p0.x) * inv0, (c[1] + p0.y) * inv0);
                *(float2*)&out[(size_t)(i0 + r0 + 8) * DOUT + col] =
                    make_float2((c[2] + p1.x) * inv1, (c[3] + p1.y) * inv1);
            }
        }
    }
}

// ============================================================
extern "C" void kernel_launch(void* const* d_in, const int* in_sizes, int n_in,
                              void* d_out, int out_size)
{
    const float* feat = (const float*)d_in[0];
    const int*   adj  = (const int*)d_in[1];
    const float* W    = (const float*)d_in[2];
    const float* b    = (const float*)d_in[3];
    const float* w1   = (const float*)d_in[4];
    const float* b1   = (const float*)d_in[5];
    const float* w2   = (const float*)d_in[6];
    const float* b2   = (const float*)d_in[7];
    float* out = (float*)d_out;

    static bool attr_set = false;
    if (!attr_set) {
        cudaFuncSetAttribute(attn_mma_kernel,
                             cudaFuncAttributeMaxDynamicSharedMemorySize, ATTN_SMEM);
        attr_set = true;
    }

    gemm_h_kernel<<<NN / 64, 256>>>(feat, W, b);
    prep_kernel<<<NN / 8, 256>>>(w1, b1, w2, b2);
    convert_hT_kernel<<<dim3(NN / 32, DOUT / 32), 256>>>();
    attn_mma_kernel<<<NN / 64, 512, ATTN_SMEM>>>(adj, out);
}

// round 10
// speedup vs baseline: 1.4111x; 1.0002x over previous
#include <cuda_runtime.h>
#include <cuda_fp16.h>
#include <math.h>
#include <cstdint>

#define NN   8192
#define DIN  256
#define DOUT 128

// ---------------- scratch ----------------
__device__ float g_h[NN * DOUT];                 // 4 MB fp32 h
__device__ float g_a1[NN], g_a2[NN];
__device__ float g_e1p[NN], g_e1n[NN];           // exp(a1), exp(0.01*a1)
__device__ float g_e2p[NN], g_e2n[NN];           // exp(a2), exp(0.01*a2)
__device__ unsigned short g_hTf[DOUT * NN];      // fp16 hT [d][j]

// ---------------- helpers ----------------
__device__ __forceinline__ uint32_t smem_u32(const void* p) {
    uint32_t a;
    asm("{ .reg .u64 t; cvta.to.shared.u64 t, %1; cvt.u32.u64 %0, t; }" : "=r"(a) : "l"(p));
    return a;
}
#define LDSM4(r0, r1, r2, r3, addr)                                            \
    asm volatile("ldmatrix.sync.aligned.m8n8.x4.shared.b16 {%0,%1,%2,%3}, [%4];" \
        : "=r"(r0), "=r"(r1), "=r"(r2), "=r"(r3) : "r"(addr))
#define MMA_F16(c, a, b0, b1)                                                  \
    asm volatile("mma.sync.aligned.m16n8k16.row.col.f32.f16.f16.f32 "          \
        "{%0,%1,%2,%3},{%4,%5,%6,%7},{%8,%9},{%0,%1,%2,%3};"                   \
        : "+f"((c)[0]), "+f"((c)[1]), "+f"((c)[2]), "+f"((c)[3])               \
        : "r"((a)[0]), "r"((a)[1]), "r"((a)[2]), "r"((a)[3]), "r"(b0), "r"(b1))
#define CP16(dst, src)                                                         \
    asm volatile("cp.async.ca.shared.global [%0], [%1], 16;"                   \
        :: "r"(dst), "l"(src) : "memory")
#define CP_COMMIT() asm volatile("cp.async.commit_group;" ::: "memory")
#define CP_WAIT0()  asm volatile("cp.async.wait_group 0;" ::: "memory")
#define BARH(id)    asm volatile("bar.sync %0, 256;" :: "r"(id) : "memory")

// ============================================================
// Kernel 1: h = feat @ W^T + b
// ============================================================
__global__ __launch_bounds__(256) void gemm_h_kernel(
    const float* __restrict__ feat, const float* __restrict__ W, const float* __restrict__ bias)
{
    __shared__ float fs[64][32];
    __shared__ float ws[32][132];
    const int t = threadIdx.x;
    const int i0 = blockIdx.x * 64;
    const int ty = t >> 4, tx = t & 15;
    float acc[4][8];
#pragma unroll
    for (int r = 0; r < 4; r++)
#pragma unroll
        for (int c = 0; c < 8; c++) acc[r][c] = 0.f;

    for (int k0 = 0; k0 < DIN; k0 += 32) {
#pragma unroll
        for (int v = 0; v < 2; v++) {
            int f = v * 256 + t, row = f >> 3, off = (f & 7) * 4;
            *(float4*)&fs[row][off] = *(const float4*)&feat[(size_t)(i0 + row) * DIN + k0 + off];
        }
        {
            int c = t >> 1, half = (t & 1) * 16;
#pragma unroll
            for (int q = 0; q < 4; q++) {
                float4 wv = *(const float4*)&W[(size_t)c * DIN + k0 + half + q * 4];
                ws[half + q * 4 + 0][c] = wv.x; ws[half + q * 4 + 1][c] = wv.y;
                ws[half + q * 4 + 2][c] = wv.z; ws[half + q * 4 + 3][c] = wv.w;
            }
        }
        __syncthreads();
#pragma unroll
        for (int kk = 0; kk < 32; kk++) {
            float a[4];
#pragma unroll
            for (int r = 0; r < 4; r++) a[r] = fs[ty * 4 + r][kk];
            float4 b0 = *(const float4*)&ws[kk][tx * 8];
            float4 b1 = *(const float4*)&ws[kk][tx * 8 + 4];
            float bb[8] = {b0.x, b0.y, b0.z, b0.w, b1.x, b1.y, b1.z, b1.w};
#pragma unroll
            for (int r = 0; r < 4; r++)
#pragma unroll
                for (int c = 0; c < 8; c++) acc[r][c] += a[r] * bb[c];
        }
        __syncthreads();
    }
#pragma unroll
    for (int r = 0; r < 4; r++) {
        int gi = i0 + ty * 4 + r;
#pragma unroll
        for (int c = 0; c < 8; c++)
            g_h[(size_t)gi * DOUT + tx * 8 + c] = acc[r][c] + bias[tx * 8 + c];
    }
}

// ============================================================
// Kernel 2: a1,a2 + factorized exp tables
// ============================================================
__global__ __launch_bounds__(256) void prep_kernel(
    const float* __restrict__ w1, const float* __restrict__ b1,
    const float* __restrict__ w2, const float* __restrict__ b2)
{
    const int warp = threadIdx.x >> 5, lane = threadIdx.x & 31;
    const int i = blockIdx.x * 8 + warp;
    float s1 = 0.f, s2 = 0.f;
#pragma unroll
    for (int d = lane; d < DOUT; d += 32) {
        float hv = g_h[(size_t)i * DOUT + d];
        s1 += hv * w1[d]; s2 += hv * w2[d];
    }
#pragma unroll
    for (int o = 16; o > 0; o >>= 1) {
        s1 += __shfl_xor_sync(0xffffffffu, s1, o);
        s2 += __shfl_xor_sync(0xffffffffu, s2, o);
    }
    if (lane == 0) {
        float a1 = s1 + b1[0], a2 = s2 + b2[0];
        g_a1[i] = a1; g_a2[i] = a2;
        g_e1p[i] = expf(a1); g_e1n[i] = expf(0.01f * a1);
        g_e2p[i] = expf(a2); g_e2n[i] = expf(0.01f * a2);
    }
}

// ============================================================
// Kernel 3: transpose h -> fp16 hT [d][j]
// ============================================================
__global__ __launch_bounds__(256) void convert_hT_kernel()
{
    __shared__ float s[32][33];
    const int i0 = blockIdx.x * 32, d0 = blockIdx.y * 32;
    const int lx = threadIdx.x & 31, ly = threadIdx.x >> 5;
#pragma unroll
    for (int q = 0; q < 4; q++) {
        int il = ly + q * 8;
        s[il][lx] = g_h[(size_t)(i0 + il) * DOUT + d0 + lx];
    }
    __syncthreads();
#pragma unroll
    for (int q = 0; q < 4; q++) {
        int dl = ly + q * 8;
        __half hv = __float2half_rn(s[lx][dl]);
        g_hTf[(size_t)(d0 + dl) * NN + i0 + lx] = *reinterpret_cast<unsigned short*>(&hv);
    }
}

// ============================================================
// Kernel 4: fused attention, two independent 256-thread sub-CTAs.
// 128 blocks x 512 threads; CTA M=64 x N=128.
// Half h (warps 8h..8h+7) handles j in [h*4096, (h+1)*4096), KT=64,
// 64 iters, own double buffer + named barriers (1,2)/(3,4).
// SMEM: half h at h*49152; stage s at s*24576: A 8K | B 16K.
// Partial accumulators + denominators merged at the end.
// ============================================================
#define KT      64
#define HITERS  (4096 / KT)
#define HALF_B  49152
#define STAGE_B 24576
#define A_T     0
#define B_T     8192
#define ATTN_SMEM (2 * HALF_B)

__global__ __launch_bounds__(512) void attn_mma_kernel(
    const int* __restrict__ adj, float* __restrict__ out)
{
    extern __shared__ char smem[];
    __shared__ float den_s2[2][64];
    const uint32_t sb = smem_u32(smem);
    const int t = threadIdx.x, lane = t & 31, wid = t >> 5;
    const int i0 = blockIdx.x * 64;
    const int half = wid >> 3;               // 0 or 1
    const int t2 = t & 255;                  // id within half
    const int jbase = half * 4096;
    const uint32_t hb = (uint32_t)half * HALF_B;
    const int bar0 = 1 + 2 * half, bar1 = 2 + 2 * half;

    // ---- weight-gen mapping: rows rq+16u (u<4), j's jq*4..+3 (within half) ----
    const int jq = t2 & 15, rq = t2 >> 4;
    float a1r[4], e1pv[4], e1nv[4], den[4];
    const int* adjp[4];
    uint32_t aSts[4];
#pragma unroll
    for (int u = 0; u < 4; u++) {
        int row = rq + 16 * u;
        int gi = i0 + row;
        a1r[u] = g_a1[gi]; e1pv[u] = g_e1p[gi]; e1nv[u] = g_e1n[gi];
        den[u] = 0.f;
        adjp[u] = adj + (size_t)gi * NN + jbase + jq * 4;
        aSts[u] = row * 128 + ((jq * 8) ^ ((row & 7) << 4));
    }

    // ---- B cp.async mapping: row bn (=d, 128), half-row bh (64B) ----
    const int bn = t2 >> 1, bh = t2 & 1;
    const unsigned short* srcB = g_hTf + (size_t)bn * NN + jbase + bh * 32;
    uint32_t bOff[4];
#pragma unroll
    for (int q = 0; q < 4; q++)
        bOff[q] = bn * 128 + (((uint32_t)(bh * 64 + q * 16)) ^ ((bn & 7) << 4));

    // ---- mma mapping: 8 warps/half, 2m x 4n, warp m32n32, all 4 ksteps ----
    const int w8 = wid & 7;
    const int wm = w8 >> 2, wn = w8 & 3;
    uint32_t aRowOff[2], bRowOff[2];
#pragma unroll
    for (int m = 0; m < 2; m++)
        aRowOff[m] = (uint32_t)(wm * 32 + m * 16 + (lane & 15)) * 128;
#pragma unroll
    for (int p = 0; p < 2; p++)
        bRowOff[p] = (uint32_t)(wn * 32 + p * 16 + (lane & 7) + ((lane >> 4) << 3)) * 128;
    const uint32_t mXor = (lane & 7) << 4;
    const uint32_t aCol = (lane >> 4) << 4;
    const uint32_t bCol = (lane & 8) << 1;

    float acc[32];
#pragma unroll
    for (int i = 0; i < 32; i++) acc[i] = 0.f;

    // ---- prefetch regs (tile k) ----
    int4 adjR[4]; float4 a2R, epR, enR;
    auto prefetch = [&](int J0) {
#pragma unroll
        for (int u = 0; u < 4; u++) adjR[u] = *(const int4*)(adjp[u] + J0);
        a2R = *(const float4*)&g_a2[jbase + J0 + jq * 4];
        epR = *(const float4*)&g_e2p[jbase + J0 + jq * 4];
        enR = *(const float4*)&g_e2n[jbase + J0 + jq * 4];
    };
    auto cpB = [&](uint32_t stb, int J0) {
#pragma unroll
        for (int q = 0; q < 4; q++)
            CP16(sb + hb + stb + B_T + bOff[q], (const void*)(srcB + J0 + q * 8));
        CP_COMMIT();
    };

    // ---- prologue ----
    cpB(0, 0);
    prefetch(0);

    for (int k = 0; k < HITERS; k++) {
        const uint32_t stb = (k & 1) ? STAGE_B : 0;
        const uint32_t ostb = STAGE_B - stb;

        // ---- compute weights for tile k (regs prefetched >1 MMA-phase ago) ----
        uint2 whi[4];
        {
            float a2a[4] = {a2R.x, a2R.y, a2R.z, a2R.w};
            float epa[4] = {epR.x, epR.y, epR.z, epR.w};
            float ena[4] = {enR.x, enR.y, enR.z, enR.w};
#pragma unroll
            for (int u = 0; u < 4; u++) {
                int avi[4] = {adjR[u].x, adjR[u].y, adjR[u].z, adjR[u].w};
                float w[4];
#pragma unroll
                for (int q = 0; q < 4; q++) {
                    float ta = a1r[u] + a2a[q];
                    float e1 = (ta >= 0.f) ? e1pv[u] : e1nv[u];
                    float e2 = (ta >= 0.f) ? epa[q] : ena[q];
                    float wq = e1 * e2;
                    wq = avi[q] ? wq : 0.f;
                    den[u] += wq;
                    w[q] = wq;
                }
                __half2 p0 = __floats2half2_rn(w[0], w[1]);
                __half2 p1 = __floats2half2_rn(w[2], w[3]);
                whi[u] = make_uint2(*reinterpret_cast<uint32_t*>(&p0),
                                    *reinterpret_cast<uint32_t*>(&p1));
            }
        }

        BARH(bar0);        // stage stb free (readers of iter k-2 done)
#pragma unroll
        for (int u = 0; u < 4; u++)
            *(uint2*)(smem + hb + stb + A_T + aSts[u]) = whi[u];
        CP_WAIT0();        // B(k) landed
        BARH(bar1);        // A+B visible to all half warps

        // issue next tile's loads EARLY so latency hides under MMA + weight-gen
        if (k + 1 < HITERS) { cpB(ostb, (k + 1) * KT); prefetch((k + 1) * KT); }

        // ---- mma: 4 k16 steps ----
        const uint32_t ab = sb + hb + stb;
#pragma unroll
        for (int si = 0; si < 4; si++) {
            const uint32_t cs = si * 32;
            uint32_t aa[2][4], bb[2][4];
            const uint32_t ca = (cs + aCol) ^ mXor;
            const uint32_t cb = (cs + bCol) ^ mXor;
#pragma unroll
            for (int m = 0; m < 2; m++)
                LDSM4(aa[m][0], aa[m][1], aa[m][2], aa[m][3], ab + A_T + aRowOff[m] + ca);
#pragma unroll
            for (int p = 0; p < 2; p++)
                LDSM4(bb[p][0], bb[p][1], bb[p][2], bb[p][3], ab + B_T + bRowOff[p] + cb);
#pragma unroll
            for (int m = 0; m < 2; m++)
#pragma unroll
                for (int nt = 0; nt < 4; nt++) {
                    float* c = &acc[(m * 4 + nt) * 4];
                    uint32_t b0 = bb[nt >> 1][(nt & 1) * 2], b1 = bb[nt >> 1][(nt & 1) * 2 + 1];
                    MMA_F16(c, aa[m], b0, b1);
                }
        }
    }

    // ---- denominator: reduce over jq (lane&15) ----
#pragma unroll
    for (int o = 8; o > 0; o >>= 1)
#pragma unroll
        for (int u = 0; u < 4; u++) den[u] += __shfl_xor_sync(0xffffffffu, den[u], o);
    if ((lane & 15) == 0)
#pragma unroll
        for (int u = 0; u < 4; u++) den_s2[half][rq + 16 * u] = den[u];

    // ---- merge halves ----
    float* out_s = (float*)smem;   // 64 x 130 floats (buffers dead)
    __syncthreads();
    if (half == 1) {
#pragma unroll
        for (int m = 0; m < 2; m++) {
            int r0 = wm * 32 + m * 16 + (lane >> 2);
#pragma unroll
            for (int nt = 0; nt < 4; nt++) {
                float* c = &acc[(m * 4 + nt) * 4];
                int col = wn * 32 + nt * 8 + (lane & 3) * 2;
                *(float2*)&out_s[r0 * 130 + col]       = make_float2(c[0], c[1]);
                *(float2*)&out_s[(r0 + 8) * 130 + col] = make_float2(c[2], c[3]);
            }
        }
    }
    __syncthreads();
    if (half == 0) {
#pragma unroll
        for (int m = 0; m < 2; m++) {
            int r0 = wm * 32 + m * 16 + (lane >> 2);
            float inv0 = 1.0f / (den_s2[0][r0]     + den_s2[1][r0]);
            float inv1 = 1.0f / (den_s2[0][r0 + 8] + den_s2[1][r0 + 8]);
#pragma unroll
            for (int nt = 0; nt < 4; nt++) {
                float* c = &acc[(m * 4 + nt) * 4];
                int col = wn * 32 + nt * 8 + (lane & 3) * 2;
                float2 p0 = *(const float2*)&out_s[r0 * 130 + col];
                float2 p1 = *(const float2*)&out_s[(r0 + 8) * 130 + col];
                *(float2*)&out[(size_t)(i0 + r0) * DOUT + col] =
                    make_float2((c[0] + p0.x) * inv0, (c[1] + p0.y) * inv0);
                *(float2*)&out[(size_t)(i0 + r0 + 8) * DOUT + col] =
                    make_float2((c[2] + p1.x) * inv1, (c[3] + p1.y) * inv1);
            }
        }
    }
}

// ============================================================
extern "C" void kernel_launch(void* const* d_in, const int* in_sizes, int n_in,
                              void* d_out, int out_size)
{
    const float* feat = (const float*)d_in[0];
    const int*   adj  = (const int*)d_in[1];
    const float* W    = (const float*)d_in[2];
    const float* b    = (const float*)d_in[3];
    const float* w1   = (const float*)d_in[4];
    const float* b1   = (const float*)d_in[5];
    const float* w2   = (const float*)d_in[6];
    const float* b2   = (const float*)d_in[7];
    float* out = (float*)d_out;

    static bool attr_set = false;
    if (!attr_set) {
        cudaFuncSetAttribute(attn_mma_kernel,
                             cudaFuncAttributeMaxDynamicSharedMemorySize, ATTN_SMEM);
        attr_set = true;
    }

    gemm_h_kernel<<<NN / 64, 256>>>(feat, W, b);
    prep_kernel<<<NN / 8, 256>>>(w1, b1, w2, b2);
    convert_hT_kernel<<<dim3(NN / 32, DOUT / 32), 256>>>();
    attn_mma_kernel<<<NN / 64, 512, ATTN_SMEM>>>(adj, out);
}

// round 11
// speedup vs baseline: 1.6271x; 1.1531x over previous
#include <cuda_runtime.h>
#include <cuda_fp16.h>
#include <math.h>
#include <cstdint>

#define NN   8192
#define DIN  256
#define DOUT 128

// ---------------- scratch ----------------
__device__ float g_a1[NN], g_a2[NN];
__device__ float g_e1p[NN], g_e1n[NN];           // exp(a1), exp(0.01*a1)
__device__ float g_e2p[NN], g_e2n[NN];           // exp(a2), exp(0.01*a2)
__device__ unsigned short g_hTf[DOUT * NN];      // fp16 hT [d][j]

// ---------------- helpers ----------------
__device__ __forceinline__ uint32_t smem_u32(const void* p) {
    uint32_t a;
    asm("{ .reg .u64 t; cvta.to.shared.u64 t, %1; cvt.u32.u64 %0, t; }" : "=r"(a) : "l"(p));
    return a;
}
__device__ __forceinline__ uint32_t pack_bf16x2(float lo, float hi) {
    uint32_t r;
    asm("cvt.rn.bf16x2.f32 %0, %1, %2;" : "=r"(r) : "f"(hi), "f"(lo));
    return r;
}
#define LDSM4(r0, r1, r2, r3, addr)                                            \
    asm volatile("ldmatrix.sync.aligned.m8n8.x4.shared.b16 {%0,%1,%2,%3}, [%4];" \
        : "=r"(r0), "=r"(r1), "=r"(r2), "=r"(r3) : "r"(addr))
#define MMA_F16(c, a, b0, b1)                                                  \
    asm volatile("mma.sync.aligned.m16n8k16.row.col.f32.f16.f16.f32 "          \
        "{%0,%1,%2,%3},{%4,%5,%6,%7},{%8,%9},{%0,%1,%2,%3};"                   \
        : "+f"((c)[0]), "+f"((c)[1]), "+f"((c)[2]), "+f"((c)[3])               \
        : "r"((a)[0]), "r"((a)[1]), "r"((a)[2]), "r"((a)[3]), "r"(b0), "r"(b1))
#define MMA_BF16(c, a, b0, b1)                                                 \
    asm volatile("mma.sync.aligned.m16n8k16.row.col.f32.bf16.bf16.f32 "        \
        "{%0,%1,%2,%3},{%4,%5,%6,%7},{%8,%9},{%0,%1,%2,%3};"                   \
        : "+f"((c)[0]), "+f"((c)[1]), "+f"((c)[2]), "+f"((c)[3])               \
        : "r"((a)[0]), "r"((a)[1]), "r"((a)[2]), "r"((a)[3]), "r"(b0), "r"(b1))
#define CP16(dst, src)                                                         \
    asm volatile("cp.async.ca.shared.global [%0], [%1], 16;"                   \
        :: "r"(dst), "l"(src) : "memory")
#define CP_COMMIT() asm volatile("cp.async.commit_group;" ::: "memory")
#define CP_WAIT0()  asm volatile("cp.async.wait_group 0;" ::: "memory")
#define BARH(id)    asm volatile("bar.sync %0, 256;" :: "r"(id) : "memory")

// ============================================================
// Kernel 1 (fused front-end): h = feat @ W^T + b via bf16 3-product
// HMMA, then in-SMEM: a1/a2 + exp tables + fp16 hT write.
// 128 blocks x 256 threads; block = 64 rows. KK=64, 4 k-tiles.
// SMEM: A_hi 8K | A_lo 8K | B_hi 16K | B_lo 16K | h_s 64x132 f32
// ============================================================
#define FA_HI 0
#define FA_LO 8192
#define FB_HI 16384
#define FB_LO 32768
#define FH    49152
#define FF_SMEM (FH + 64 * 132 * 4)

__global__ __launch_bounds__(256) void fused_front_kernel(
    const float* __restrict__ feat, const float* __restrict__ W,
    const float* __restrict__ bias,
    const float* __restrict__ w1, const float* __restrict__ b1,
    const float* __restrict__ w2, const float* __restrict__ b2)
{
    extern __shared__ char smem[];
    const uint32_t sb = smem_u32(smem);
    const int t = threadIdx.x, lane = t & 31, wid = t >> 5;
    const int i0 = blockIdx.x * 64;

    // load mappings
    const int ft_r = t >> 2, ft_k = (t & 3) * 16;      // feat: row, 16 k's
    const int wt_r = t >> 1, wt_k = (t & 1) * 32;      // W: row, 32 k's

    // mma mapping (same fragment scheme as attn kernel)
    const int wm = wid >> 2, wn = wid & 3;
    uint32_t aRowOff[2], bRowOff[2];
#pragma unroll
    for (int m = 0; m < 2; m++)
        aRowOff[m] = (uint32_t)(wm * 32 + m * 16 + (lane & 15)) * 128;
#pragma unroll
    for (int p = 0; p < 2; p++)
        bRowOff[p] = (uint32_t)(wn * 32 + p * 16 + (lane & 7) + ((lane >> 4) << 3)) * 128;
    const uint32_t mXor = (lane & 7) << 4;
    const uint32_t aCol = (lane >> 4) << 4;
    const uint32_t bCol = (lane & 8) << 1;

    float acc[32];
#pragma unroll
    for (int i = 0; i < 32; i++) acc[i] = 0.f;

    for (int kt = 0; kt < 4; kt++) {
        __syncthreads();
        // ---- feat tile -> bf16 hi/lo ----
        {
            const float* src = feat + (size_t)(i0 + ft_r) * DIN + kt * 64 + ft_k;
            uint32_t hi[8], lo[8];
#pragma unroll
            for (int q = 0; q < 4; q++) {
                float4 v = *(const float4*)(src + q * 4);
                uint32_t u0 = __float_as_uint(v.x), u1 = __float_as_uint(v.y);
                uint32_t u2 = __float_as_uint(v.z), u3 = __float_as_uint(v.w);
                hi[2 * q]     = __byte_perm(u0, u1, 0x7632);
                hi[2 * q + 1] = __byte_perm(u2, u3, 0x7632);
                lo[2 * q]     = pack_bf16x2(v.x - __uint_as_float(u0 & 0xffff0000u),
                                            v.y - __uint_as_float(u1 & 0xffff0000u));
                lo[2 * q + 1] = pack_bf16x2(v.z - __uint_as_float(u2 & 0xffff0000u),
                                            v.w - __uint_as_float(u3 & 0xffff0000u));
            }
#pragma unroll
            for (int c = 0; c < 2; c++) {
                uint32_t off = ft_r * 128 + (((uint32_t)(ft_k * 2 + c * 16)) ^ ((ft_r & 7) << 4));
                *(uint4*)(smem + FA_HI + off) = make_uint4(hi[4*c], hi[4*c+1], hi[4*c+2], hi[4*c+3]);
                *(uint4*)(smem + FA_LO + off) = make_uint4(lo[4*c], lo[4*c+1], lo[4*c+2], lo[4*c+3]);
            }
        }
        // ---- W tile -> bf16 hi/lo ----
        {
            const float* src = W + (size_t)wt_r * DIN + kt * 64 + wt_k;
            uint32_t hi[16], lo[16];
#pragma unroll
            for (int q = 0; q < 8; q++) {
                float4 v = *(const float4*)(src + q * 4);
                uint32_t u0 = __float_as_uint(v.x), u1 = __float_as_uint(v.y);
                uint32_t u2 = __float_as_uint(v.z), u3 = __float_as_uint(v.w);
                hi[2 * q]     = __byte_perm(u0, u1, 0x7632);
                hi[2 * q + 1] = __byte_perm(u2, u3, 0x7632);
                lo[2 * q]     = pack_bf16x2(v.x - __uint_as_float(u0 & 0xffff0000u),
                                            v.y - __uint_as_float(u1 & 0xffff0000u));
                lo[2 * q + 1] = pack_bf16x2(v.z - __uint_as_float(u2 & 0xffff0000u),
                                            v.w - __uint_as_float(u3 & 0xffff0000u));
            }
#pragma unroll
            for (int c = 0; c < 4; c++) {
                uint32_t off = wt_r * 128 + (((uint32_t)(wt_k * 2 + c * 16)) ^ ((wt_r & 7) << 4));
                *(uint4*)(smem + FB_HI + off) = make_uint4(hi[4*c], hi[4*c+1], hi[4*c+2], hi[4*c+3]);
                *(uint4*)(smem + FB_LO + off) = make_uint4(lo[4*c], lo[4*c+1], lo[4*c+2], lo[4*c+3]);
            }
        }
        __syncthreads();

        // ---- mma: 4 k16 steps, 3 products ----
#pragma unroll
        for (int si = 0; si < 4; si++) {
            const uint32_t cs = si * 32;
            uint32_t ah[2][4], al[2][4], bh[2][4], bl[2][4];
            const uint32_t ca = (cs + aCol) ^ mXor;
            const uint32_t cb = (cs + bCol) ^ mXor;
#pragma unroll
            for (int m = 0; m < 2; m++) {
                LDSM4(ah[m][0], ah[m][1], ah[m][2], ah[m][3], sb + FA_HI + aRowOff[m] + ca);
                LDSM4(al[m][0], al[m][1], al[m][2], al[m][3], sb + FA_LO + aRowOff[m] + ca);
            }
#pragma unroll
            for (int p = 0; p < 2; p++) {
                LDSM4(bh[p][0], bh[p][1], bh[p][2], bh[p][3], sb + FB_HI + bRowOff[p] + cb);
                LDSM4(bl[p][0], bl[p][1], bl[p][2], bl[p][3], sb + FB_LO + bRowOff[p] + cb);
            }
#pragma unroll
            for (int m = 0; m < 2; m++)
#pragma unroll
                for (int nt = 0; nt < 4; nt++) {
                    float* c = &acc[(m * 4 + nt) * 4];
                    uint32_t b0 = bh[nt >> 1][(nt & 1) * 2], b1 = bh[nt >> 1][(nt & 1) * 2 + 1];
                    MMA_BF16(c, ah[m], b0, b1);
                    MMA_BF16(c, al[m], b0, b1);
                    uint32_t d0 = bl[nt >> 1][(nt & 1) * 2], d1 = bl[nt >> 1][(nt & 1) * 2 + 1];
                    MMA_BF16(c, ah[m], d0, d1);
                }
        }
    }

    // ---- epilogue 1: h block (+bias) -> smem h_s[64][132] ----
    float* h_s = (float*)(smem + FH);
    __syncthreads();
#pragma unroll
    for (int m = 0; m < 2; m++) {
        int r0 = wm * 32 + m * 16 + (lane >> 2);
#pragma unroll
        for (int nt = 0; nt < 4; nt++) {
            float* c = &acc[(m * 4 + nt) * 4];
            int col = wn * 32 + nt * 8 + (lane & 3) * 2;
            float b0v = bias[col], b1v = bias[col + 1];
            *(float2*)&h_s[r0 * 132 + col]       = make_float2(c[0] + b0v, c[1] + b1v);
            *(float2*)&h_s[(r0 + 8) * 132 + col] = make_float2(c[2] + b0v, c[3] + b1v);
        }
    }
    __syncthreads();

    // ---- epilogue 2: a1/a2 + exp tables (warp wid -> rows wid*8..+7) ----
    {
        const int g = lane >> 2, dsub = lane & 3;
        const int row = wid * 8 + g;
        float s1 = 0.f, s2 = 0.f;
#pragma unroll
        for (int d = dsub; d < DOUT; d += 4) {
            float hv = h_s[row * 132 + d];
            s1 += hv * w1[d]; s2 += hv * w2[d];
        }
        s1 += __shfl_xor_sync(0xffffffffu, s1, 1);
        s1 += __shfl_xor_sync(0xffffffffu, s1, 2);
        s2 += __shfl_xor_sync(0xffffffffu, s2, 1);
        s2 += __shfl_xor_sync(0xffffffffu, s2, 2);
        if (dsub == 0) {
            int gi = i0 + row;
            float a1 = s1 + b1[0], a2 = s2 + b2[0];
            g_a1[gi] = a1; g_a2[gi] = a2;
            g_e1p[gi] = expf(a1); g_e1n[gi] = expf(0.01f * a1);
            g_e2p[gi] = expf(a2); g_e2n[gi] = expf(0.01f * a2);
        }
    }

    // ---- epilogue 3: transposed fp16 hT write: hTf[d][i0+j] ----
    {
        const int d = t >> 1, jh = t & 1;
        unsigned short* dst = g_hTf + (size_t)d * NN + i0 + jh * 32;
#pragma unroll
        for (int p = 0; p < 16; p++) {
            __half h0 = __float2half_rn(h_s[(jh * 32 + 2 * p) * 132 + d]);
            __half h1 = __float2half_rn(h_s[(jh * 32 + 2 * p + 1) * 132 + d]);
            uint32_t pk = ((uint32_t)*reinterpret_cast<unsigned short*>(&h1) << 16) |
                          (uint32_t)*reinterpret_cast<unsigned short*>(&h0);
            *(uint32_t*)(dst + 2 * p) = pk;
        }
    }
}

// ============================================================
// Kernel 2: fused attention (UNCHANGED from R9 winner).
// Two independent 256-thread sub-CTAs, KT=64, double buffer each.
// ============================================================
#define KT      64
#define HITERS  (4096 / KT)
#define HALF_B  49152
#define STAGE_B 24576
#define A_T     0
#define B_T     8192
#define ATTN_SMEM (2 * HALF_B)

__global__ __launch_bounds__(512) void attn_mma_kernel(
    const int* __restrict__ adj, float* __restrict__ out)
{
    extern __shared__ char smem[];
    __shared__ float den_s2[2][64];
    const uint32_t sb = smem_u32(smem);
    const int t = threadIdx.x, lane = t & 31, wid = t >> 5;
    const int i0 = blockIdx.x * 64;
    const int half = wid >> 3;
    const int t2 = t & 255;
    const int jbase = half * 4096;
    const uint32_t hb = (uint32_t)half * HALF_B;
    const int bar0 = 1 + 2 * half, bar1 = 2 + 2 * half;

    const int jq = t2 & 15, rq = t2 >> 4;
    float a1r[4], e1pv[4], e1nv[4], den[4];
    const int* adjp[4];
    uint32_t aSts[4];
#pragma unroll
    for (int u = 0; u < 4; u++) {
        int row = rq + 16 * u;
        int gi = i0 + row;
        a1r[u] = g_a1[gi]; e1pv[u] = g_e1p[gi]; e1nv[u] = g_e1n[gi];
        den[u] = 0.f;
        adjp[u] = adj + (size_t)gi * NN + jbase + jq * 4;
        aSts[u] = row * 128 + ((jq * 8) ^ ((row & 7) << 4));
    }

    const int bn = t2 >> 1, bh = t2 & 1;
    const unsigned short* srcB = g_hTf + (size_t)bn * NN + jbase + bh * 32;
    uint32_t bOff[4];
#pragma unroll
    for (int q = 0; q < 4; q++)
        bOff[q] = bn * 128 + (((uint32_t)(bh * 64 + q * 16)) ^ ((bn & 7) << 4));

    const int w8 = wid & 7;
    const int wm = w8 >> 2, wn = w8 & 3;
    uint32_t aRowOff[2], bRowOff[2];
#pragma unroll
    for (int m = 0; m < 2; m++)
        aRowOff[m] = (uint32_t)(wm * 32 + m * 16 + (lane & 15)) * 128;
#pragma unroll
    for (int p = 0; p < 2; p++)
        bRowOff[p] = (uint32_t)(wn * 32 + p * 16 + (lane & 7) + ((lane >> 4) << 3)) * 128;
    const uint32_t mXor = (lane & 7) << 4;
    const uint32_t aCol = (lane >> 4) << 4;
    const uint32_t bCol = (lane & 8) << 1;

    float acc[32];
#pragma unroll
    for (int i = 0; i < 32; i++) acc[i] = 0.f;

    int4 adjR[4]; float4 a2R, epR, enR;
    auto prefetch = [&](int J0) {
#pragma unroll
        for (int u = 0; u < 4; u++) adjR[u] = *(const int4*)(adjp[u] + J0);
        a2R = *(const float4*)&g_a2[jbase + J0 + jq * 4];
        epR = *(const float4*)&g_e2p[jbase + J0 + jq * 4];
        enR = *(const float4*)&g_e2n[jbase + J0 + jq * 4];
    };
    auto cpB = [&](uint32_t stb, int J0) {
#pragma unroll
        for (int q = 0; q < 4; q++)
            CP16(sb + hb + stb + B_T + bOff[q], (const void*)(srcB + J0 + q * 8));
        CP_COMMIT();
    };

    cpB(0, 0);
    prefetch(0);

    for (int k = 0; k < HITERS; k++) {
        const uint32_t stb = (k & 1) ? STAGE_B : 0;
        const uint32_t ostb = STAGE_B - stb;

        uint2 whi[4];
        {
            float a2a[4] = {a2R.x, a2R.y, a2R.z, a2R.w};
            float epa[4] = {epR.x, epR.y, epR.z, epR.w};
            float ena[4] = {enR.x, enR.y, enR.z, enR.w};
#pragma unroll
            for (int u = 0; u < 4; u++) {
                int avi[4] = {adjR[u].x, adjR[u].y, adjR[u].z, adjR[u].w};
                float w[4];
#pragma unroll
                for (int q = 0; q < 4; q++) {
                    float ta = a1r[u] + a2a[q];
                    float e1 = (ta >= 0.f) ? e1pv[u] : e1nv[u];
                    float e2 = (ta >= 0.f) ? epa[q] : ena[q];
                    float wq = e1 * e2;
                    wq = avi[q] ? wq : 0.f;
                    den[u] += wq;
                    w[q] = wq;
                }
                __half2 p0 = __floats2half2_rn(w[0], w[1]);
                __half2 p1 = __floats2half2_rn(w[2], w[3]);
                whi[u] = make_uint2(*reinterpret_cast<uint32_t*>(&p0),
                                    *reinterpret_cast<uint32_t*>(&p1));
            }
        }

        BARH(bar0);
#pragma unroll
        for (int u = 0; u < 4; u++)
            *(uint2*)(smem + hb + stb + A_T + aSts[u]) = whi[u];
        CP_WAIT0();
        BARH(bar1);

        if (k + 1 < HITERS) { cpB(ostb, (k + 1) * KT); prefetch((k + 1) * KT); }

        const uint32_t ab = sb + hb + stb;
#pragma unroll
        for (int si = 0; si < 4; si++) {
            const uint32_t cs = si * 32;
            uint32_t aa[2][4], bb[2][4];
            const uint32_t ca = (cs + aCol) ^ mXor;
            const uint32_t cb = (cs + bCol) ^ mXor;
#pragma unroll
            for (int m = 0; m < 2; m++)
                LDSM4(aa[m][0], aa[m][1], aa[m][2], aa[m][3], ab + A_T + aRowOff[m] + ca);
#pragma unroll
            for (int p = 0; p < 2; p++)
                LDSM4(bb[p][0], bb[p][1], bb[p][2], bb[p][3], ab + B_T + bRowOff[p] + cb);
#pragma unroll
            for (int m = 0; m < 2; m++)
#pragma unroll
                for (int nt = 0; nt < 4; nt++) {
                    float* c = &acc[(m * 4 + nt) * 4];
                    uint32_t b0 = bb[nt >> 1][(nt & 1) * 2], b1 = bb[nt >> 1][(nt & 1) * 2 + 1];
                    MMA_F16(c, aa[m], b0, b1);
                }
        }
    }

#pragma unroll
    for (int o = 8; o > 0; o >>= 1)
#pragma unroll
        for (int u = 0; u < 4; u++) den[u] += __shfl_xor_sync(0xffffffffu, den[u], o);
    if ((lane & 15) == 0)
#pragma unroll
        for (int u = 0; u < 4; u++) den_s2[half][rq + 16 * u] = den[u];

    float* out_s = (float*)smem;
    __syncthreads();
    if (half == 1) {
#pragma unroll
        for (int m = 0; m < 2; m++) {
            int r0 = wm * 32 + m * 16 + (lane >> 2);
#pragma unroll
            for (int nt = 0; nt < 4; nt++) {
                float* c = &acc[(m * 4 + nt) * 4];
                int col = wn * 32 + nt * 8 + (lane & 3) * 2;
                *(float2*)&out_s[r0 * 130 + col]       = make_float2(c[0], c[1]);
                *(float2*)&out_s[(r0 + 8) * 130 + col] = make_float2(c[2], c[3]);
            }
        }
    }
    __syncthreads();
    if (half == 0) {
#pragma unroll
        for (int m = 0; m < 2; m++) {
            int r0 = wm * 32 + m * 16 + (lane >> 2);
            float inv0 = 1.0f / (den_s2[0][r0]     + den_s2[1][r0]);
            float inv1 = 1.0f / (den_s2[0][r0 + 8] + den_s2[1][r0 + 8]);
#pragma unroll
            for (int nt = 0; nt < 4; nt++) {
                float* c = &acc[(m * 4 + nt) * 4];
                int col = wn * 32 + nt * 8 + (lane & 3) * 2;
                float2 p0 = *(const float2*)&out_s[r0 * 130 + col];
                float2 p1 = *(const float2*)&out_s[(r0 + 8) * 130 + col];
                *(float2*)&out[(size_t)(i0 + r0) * DOUT + col] =
                    make_float2((c[0] + p0.x) * inv0, (c[1] + p0.y) * inv0);
                *(float2*)&out[(size_t)(i0 + r0 + 8) * DOUT + col] =
                    make_float2((c[2] + p1.x) * inv1, (c[3] + p1.y) * inv1);
            }
        }
    }
}

// ============================================================
extern "C" void kernel_launch(void* const* d_in, const int* in_sizes, int n_in,
                              void* d_out, int out_size)
{
    const float* feat = (const float*)d_in[0];
    const int*   adj  = (const int*)d_in[1];
    const float* W    = (const float*)d_in[2];
    const float* b    = (const float*)d_in[3];
    const float* w1   = (const float*)d_in[4];
    const float* b1   = (const float*)d_in[5];
    const float* w2   = (const float*)d_in[6];
    const float* b2   = (const float*)d_in[7];
    float* out = (float*)d_out;

    static bool attr_set = false;
    if (!attr_set) {
        cudaFuncSetAttribute(fused_front_kernel,
                             cudaFuncAttributeMaxDynamicSharedMemorySize, FF_SMEM);
        cudaFuncSetAttribute(attn_mma_kernel,
                             cudaFuncAttributeMaxDynamicSharedMemorySize, ATTN_SMEM);
        attr_set = true;
    }

    fused_front_kernel<<<NN / 64, 256, FF_SMEM>>>(feat, W, b, w1, b1, w2, b2);
    attn_mma_kernel<<<NN / 64, 512, ATTN_SMEM>>>(adj, out);
}